// round 6
// baseline (speedup 1.0000x reference)
#include <cuda_runtime.h>
#include <math.h>

static constexpr int NE = 8;
static constexpr int NT = 256;
static constexpr int ND = 2048;
static constexpr int NH = 8192;

// 64MB scratch for h1 / mid  (__device__ global: allocation-guard safe)
__device__ float g_s1[(size_t)NE * NT * NH];

__device__ __forceinline__ unsigned f2tf(float x) {
    unsigned r;
    asm("cvt.rna.tf32.f32 %0, %1;" : "=r"(r) : "f"(x));
    return r;
}

__device__ __forceinline__ float silu(float x) {
    return x / (1.0f + __expf(-x));
}

// C[NT, Nc] = A[NT, Kc] @ B   (per expert, blockIdx.z = expert)
// BMODE 0: B is [Kc, Nc] row-major (n contiguous)  -> up/gate proj (w1/w3)
// BMODE 1: B is [Nc, Kc] row-major (k contiguous)  -> down proj (w2, used transposed)
// EPI   0: C = acc
// EPI   1: C = silu(Saux) * acc      (Saux read at same index as C)
template<int BMODE, int EPI, int Nc, int Kc>
__global__ __launch_bounds__(256, 2)
void gemm_tf32(const float* __restrict__ A, const float* __restrict__ Bg,
               const float* __restrict__ Saux, float* __restrict__ Cg)
{
    constexpr int SA = 36;                          // As row stride (pad 4): frag bank = 4g+tig, conflict-free
    constexpr int SB = (BMODE == 0) ? 136 : 36;     // Bs row stride: 136 -> bank 8*tig+g; 36 -> bank 4g+tig
    constexpr int ASZ = 128 * SA;
    constexpr int BSZ = (BMODE == 0) ? (32 * 136) : (128 * 36);

    extern __shared__ float sm[];
    float* Asb[2] = { sm,             sm + (ASZ + BSZ) };
    float* Bsb[2] = { sm + ASZ,       sm + (ASZ + BSZ) + ASZ };

    const int tid  = threadIdx.x;
    const int wid  = tid >> 5;
    const int lane = tid & 31;
    const int wm   = wid >> 2;       // 0..1  (64 rows each)
    const int wn   = wid & 3;        // 0..3  (32 cols each)
    const int g    = lane >> 2;      // groupID 0..7
    const int tig  = lane & 3;       // thread-in-group

    const int m0 = blockIdx.y * 128;
    const int n0 = blockIdx.x * 128;

    const float* Ae = A  + (size_t)blockIdx.z * NT * Kc + (size_t)m0 * Kc;
    const float* Be = Bg + (size_t)blockIdx.z * (size_t)Nc * Kc;
    float*       Ce = Cg + (size_t)blockIdx.z * NT * Nc;
    const float* Se = Saux + (size_t)blockIdx.z * NT * Nc;

    float acc[4][4][4];
    #pragma unroll
    for (int i = 0; i < 4; i++)
        #pragma unroll
        for (int j = 0; j < 4; j++)
            #pragma unroll
            for (int k = 0; k < 4; k++)
                acc[i][j][k] = 0.0f;

    // ---- staging: 128x32 A tile + B tile, with tf32 round ----
    auto stage = [&](int buf, int kt) {
        float* As = Asb[buf];
        float* Bs = Bsb[buf];
        #pragma unroll
        for (int i = 0; i < 4; i++) {
            int idx = tid + i * 256;
            int r = idx >> 3;
            int c = (idx & 7) * 4;
            float4 v = *(const float4*)(Ae + (size_t)r * Kc + kt + c);
            float4 w;
            w.x = __uint_as_float(f2tf(v.x));
            w.y = __uint_as_float(f2tf(v.y));
            w.z = __uint_as_float(f2tf(v.z));
            w.w = __uint_as_float(f2tf(v.w));
            *(float4*)&As[r * SA + c] = w;
        }
        #pragma unroll
        for (int i = 0; i < 4; i++) {
            int idx = tid + i * 256;
            if (BMODE == 0) {
                int kr = idx >> 5;
                int nc = (idx & 31) * 4;
                float4 v = *(const float4*)(Be + (size_t)(kt + kr) * Nc + n0 + nc);
                float4 w;
                w.x = __uint_as_float(f2tf(v.x));
                w.y = __uint_as_float(f2tf(v.y));
                w.z = __uint_as_float(f2tf(v.z));
                w.w = __uint_as_float(f2tf(v.w));
                *(float4*)&Bs[kr * SB + nc] = w;
            } else {
                int nr = idx >> 3;
                int kc = (idx & 7) * 4;
                float4 v = *(const float4*)(Be + (size_t)(n0 + nr) * Kc + kt + kc);
                float4 w;
                w.x = __uint_as_float(f2tf(v.x));
                w.y = __uint_as_float(f2tf(v.y));
                w.z = __uint_as_float(f2tf(v.z));
                w.w = __uint_as_float(f2tf(v.w));
                *(float4*)&Bs[nr * SB + kc] = w;
            }
        }
    };

    constexpr int NIT = Kc / 32;
    stage(0, 0);
    __syncthreads();

    #pragma unroll 1
    for (int it = 0; it < NIT; it++) {
        const int buf = it & 1;

        // prefetch next tile into the other buffer (LDGs issue before MMAs;
        // latency + cvt + STS overlap the 64 MMAs below)
        if (it + 1 < NIT) stage(buf ^ 1, (it + 1) * 32);

        const float* As = Asb[buf];
        const float* Bs = Bsb[buf];

        // ---- compute: 4 k-steps of k=8 ----
        #pragma unroll
        for (int ks = 0; ks < 4; ks++) {
            const int k8 = ks * 8;

            unsigned af[4][4];
            #pragma unroll
            for (int mi = 0; mi < 4; mi++) {
                int row = wm * 64 + mi * 16 + g;
                af[mi][0] = __float_as_uint(As[row       * SA + k8 + tig]);
                af[mi][1] = __float_as_uint(As[(row + 8) * SA + k8 + tig]);
                af[mi][2] = __float_as_uint(As[row       * SA + k8 + tig + 4]);
                af[mi][3] = __float_as_uint(As[(row + 8) * SA + k8 + tig + 4]);
            }
            unsigned bf[4][2];
            #pragma unroll
            for (int nj = 0; nj < 4; nj++) {
                int n = wn * 32 + nj * 8 + g;
                if (BMODE == 0) {
                    bf[nj][0] = __float_as_uint(Bs[(k8 + tig)     * SB + n]);
                    bf[nj][1] = __float_as_uint(Bs[(k8 + tig + 4) * SB + n]);
                } else {
                    bf[nj][0] = __float_as_uint(Bs[n * SB + k8 + tig]);
                    bf[nj][1] = __float_as_uint(Bs[n * SB + k8 + tig + 4]);
                }
            }
            #pragma unroll
            for (int mi = 0; mi < 4; mi++) {
                #pragma unroll
                for (int nj = 0; nj < 4; nj++) {
                    asm volatile(
                        "mma.sync.aligned.m16n8k8.row.col.f32.tf32.tf32.f32 "
                        "{%0,%1,%2,%3}, {%4,%5,%6,%7}, {%8,%9}, {%0,%1,%2,%3};"
                        : "+f"(acc[mi][nj][0]), "+f"(acc[mi][nj][1]),
                          "+f"(acc[mi][nj][2]), "+f"(acc[mi][nj][3])
                        : "r"(af[mi][0]), "r"(af[mi][1]), "r"(af[mi][2]), "r"(af[mi][3]),
                          "r"(bf[nj][0]), "r"(bf[nj][1]));
                }
            }
        }
        __syncthreads();   // stage(buf^1) complete + compute(buf) complete for all
    }

    // ---- epilogue ----
    #pragma unroll
    for (int mi = 0; mi < 4; mi++) {
        #pragma unroll
        for (int nj = 0; nj < 4; nj++) {
            int row = m0 + wm * 64 + mi * 16 + g;
            int col = n0 + wn * 32 + nj * 8 + tig * 2;
            size_t i00 = (size_t)row * Nc + col;
            size_t i10 = (size_t)(row + 8) * Nc + col;
            if (EPI == 0) {
                Ce[i00]     = acc[mi][nj][0];
                Ce[i00 + 1] = acc[mi][nj][1];
                Ce[i10]     = acc[mi][nj][2];
                Ce[i10 + 1] = acc[mi][nj][3];
            } else {
                float h00 = Se[i00], h01 = Se[i00 + 1];
                float h10 = Se[i10], h11 = Se[i10 + 1];
                Ce[i00]     = silu(h00) * acc[mi][nj][0];
                Ce[i00 + 1] = silu(h01) * acc[mi][nj][1];
                Ce[i10]     = silu(h10) * acc[mi][nj][2];
                Ce[i10 + 1] = silu(h11) * acc[mi][nj][3];
            }
        }
    }
}

extern "C" void kernel_launch(void* const* d_in, const int* in_sizes, int n_in,
                              void* d_out, int out_size)
{
    const float* x  = (const float*)d_in[0];
    const float* w1 = (const float*)d_in[1];
    const float* w2 = (const float*)d_in[2];
    const float* w3 = (const float*)d_in[3];
    float* out = (float*)d_out;

    float* s1 = nullptr;
    cudaGetSymbolAddress((void**)&s1, g_s1);   // no allocation; capture-safe

    // dynamic smem: 2 * (A tile + B tile)
    constexpr size_t SM0 = 2 * (128 * 36 + 32 * 136) * sizeof(float);   // 71680 (BMODE 0)
    constexpr size_t SM1 = 2 * (128 * 36 + 128 * 36) * sizeof(float);   // 73728 (BMODE 1)
    cudaFuncSetAttribute(gemm_tf32<0, 0, NH, ND>, cudaFuncAttributeMaxDynamicSharedMemorySize, SM0);
    cudaFuncSetAttribute(gemm_tf32<0, 1, NH, ND>, cudaFuncAttributeMaxDynamicSharedMemorySize, SM0);
    cudaFuncSetAttribute(gemm_tf32<1, 0, ND, NH>, cudaFuncAttributeMaxDynamicSharedMemorySize, SM1);

    dim3 blk(256);
    dim3 g0(NH / 128, NT / 128, NE);   // (64, 2, 8)
    dim3 g1(ND / 128, NT / 128, NE);   // (16, 2, 8)

    // h1 = x @ w1                                   -> s1
    gemm_tf32<0, 0, NH, ND><<<g0, blk, SM0>>>(x, w1, s1, s1);
    // mid = silu(h1) * (x @ w3)                     -> s1 (in place)
    gemm_tf32<0, 1, NH, ND><<<g0, blk, SM0>>>(x, w3, s1, s1);
    // out = mid @ w2^T
    gemm_tf32<1, 0, ND, NH><<<g1, blk, SM1>>>(s1, w2, out, out);
}

// round 8
// speedup vs baseline: 1.8579x; 1.8579x over previous
#include <cuda_runtime.h>
#include <math.h>

static constexpr int NE = 8;
static constexpr int NT = 256;
static constexpr int ND = 2048;
static constexpr int NH = 8192;

// Scratch (__device__ globals: allocation-guard safe)
__device__ float g_s1[(size_t)NE * NT * NH];   // h1 / mid (64MB)
__device__ float g_s2[(size_t)NE * NT * ND];   // tf32-rounded x (16MB)

__device__ __forceinline__ unsigned f2tf(float x) {
    unsigned r;
    asm("cvt.rna.tf32.f32 %0, %1;" : "=r"(r) : "f"(x));
    return r;
}

__device__ __forceinline__ float silu(float x) {
    return x / (1.0f + __expf(-x));
}

__device__ __forceinline__ unsigned s2u(const void* p) {
    unsigned a;
    asm("{ .reg .u64 t; cvta.to.shared.u64 t, %1; cvt.u32.u64 %0, t; }" : "=r"(a) : "l"(p));
    return a;
}

__device__ __forceinline__ void cpasync16(unsigned dst, const void* src) {
    asm volatile("cp.async.cg.shared.global [%0], [%1], 16;" :: "r"(dst), "l"(src) : "memory");
}

// Elementwise tf32 pre-round (x -> g_s2), float4 vectorized
__global__ void round_tf32(const float* __restrict__ in, float* __restrict__ out, int n4) {
    int i = blockIdx.x * blockDim.x + threadIdx.x;
    if (i < n4) {
        float4 v = ((const float4*)in)[i];
        float4 w;
        w.x = __uint_as_float(f2tf(v.x));
        w.y = __uint_as_float(f2tf(v.y));
        w.z = __uint_as_float(f2tf(v.z));
        w.w = __uint_as_float(f2tf(v.w));
        ((float4*)out)[i] = w;
    }
}

// C[NT, Nc] = A[NT, Kc] @ B   (per expert, blockIdx.z = expert)
// A is PRE-ROUNDED to tf32. B is raw fp32 (rounded at fragment load).
// BMODE 0: B is [Kc, Nc] row-major (n contiguous)  -> up/gate proj (w1/w3)
// BMODE 1: B is [Nc, Kc] row-major (k contiguous)  -> down proj (w2, transposed use)
// EPI 0: C = acc          EPI 1: C = round_tf32(silu(Saux) * acc)
template<int BMODE, int EPI, int Nc, int Kc>
__global__ __launch_bounds__(256, 2)
void gemm_tf32(const float* __restrict__ A, const float* __restrict__ Bg,
               const float* __restrict__ Saux, float* __restrict__ Cg)
{
    constexpr int SA = 36;                          // As row stride (floats); frag bank = 4g+tig
    constexpr int SB = (BMODE == 0) ? 136 : 36;     // Bs row stride
    constexpr int ASZ = 128 * SA;                   // floats
    constexpr int BSZ = (BMODE == 0) ? (32 * 136) : (128 * 36);
    constexpr int STGB = (ASZ + BSZ) * 4;           // bytes per stage

    extern __shared__ float sm[];
    const unsigned sbase = s2u(sm);

    const int tid  = threadIdx.x;
    const int wid  = tid >> 5;
    const int lane = tid & 31;
    const int wm   = wid >> 2;       // 0..1
    const int wn   = wid & 3;        // 0..3
    const int g    = lane >> 2;      // 0..7
    const int tig  = lane & 3;       // 0..3

    const int m0 = blockIdx.y * 128;
    const int n0 = blockIdx.x * 128;

    const float* Ae = A  + (size_t)blockIdx.z * NT * Kc + (size_t)m0 * Kc;
    const float* Be = Bg + (size_t)blockIdx.z * (size_t)Nc * Kc;
    float*       Ce = Cg + (size_t)blockIdx.z * NT * Nc;
    const float* Se = Saux + (size_t)blockIdx.z * NT * Nc;

    float acc[4][4][4];
    #pragma unroll
    for (int i = 0; i < 4; i++)
        #pragma unroll
        for (int j = 0; j < 4; j++)
            #pragma unroll
            for (int k = 0; k < 4; k++)
                acc[i][j][k] = 0.0f;

    // ---- async staging of one 32-wide k-tile into stage s ----
    auto stage = [&](int s, int kt) {
        const unsigned ab = sbase + (unsigned)s * STGB;
        const unsigned bb = ab + ASZ * 4;
        #pragma unroll
        for (int i = 0; i < 4; i++) {
            int idx = tid + i * 256;
            int r = idx >> 3, c = (idx & 7) * 4;
            cpasync16(ab + (r * SA + c) * 4, Ae + (size_t)r * Kc + kt + c);
        }
        #pragma unroll
        for (int i = 0; i < 4; i++) {
            int idx = tid + i * 256;
            if (BMODE == 0) {
                int kr = idx >> 5, nc = (idx & 31) * 4;
                cpasync16(bb + (kr * SB + nc) * 4, Be + (size_t)(kt + kr) * Nc + n0 + nc);
            } else {
                int nr = idx >> 3, kc = (idx & 7) * 4;
                cpasync16(bb + (nr * SB + kc) * 4, Be + (size_t)(n0 + nr) * Kc + kt + kc);
            }
        }
        asm volatile("cp.async.commit_group;" ::: "memory");
    };

    constexpr int NIT = Kc / 32;
    stage(0, 0);
    stage(1, 32);

    #pragma unroll 1
    for (int it = 0; it < NIT; it++) {
        // wait for stage `it` (FIFO group completion), then make visible CTA-wide
        if (it + 1 < NIT) {
            asm volatile("cp.async.wait_group 1;" ::: "memory");
        } else {
            asm volatile("cp.async.wait_group 0;" ::: "memory");
        }
        __syncthreads();

        // kick off copy for tile it+2 (overwrites buffer consumed at iter it-1)
        if (it + 2 < NIT) stage((it + 2) % 3, (it + 2) * 32);

        const float* As = sm + (size_t)(it % 3) * (ASZ + BSZ);
        const float* Bs = As + ASZ;

        // ---- compute: 4 k-steps of k=8 ----
        #pragma unroll
        for (int ks = 0; ks < 4; ks++) {
            const int k8 = ks * 8;

            unsigned af[4][4];
            #pragma unroll
            for (int mi = 0; mi < 4; mi++) {
                int row = wm * 64 + mi * 16 + g;
                af[mi][0] = __float_as_uint(As[row       * SA + k8 + tig]);
                af[mi][1] = __float_as_uint(As[(row + 8) * SA + k8 + tig]);
                af[mi][2] = __float_as_uint(As[row       * SA + k8 + tig + 4]);
                af[mi][3] = __float_as_uint(As[(row + 8) * SA + k8 + tig + 4]);
            }
            unsigned bf[4][2];
            #pragma unroll
            for (int nj = 0; nj < 4; nj++) {
                int n = wn * 32 + nj * 8 + g;
                if (BMODE == 0) {
                    bf[nj][0] = f2tf(Bs[(k8 + tig)     * SB + n]);
                    bf[nj][1] = f2tf(Bs[(k8 + tig + 4) * SB + n]);
                } else {
                    bf[nj][0] = f2tf(Bs[n * SB + k8 + tig]);
                    bf[nj][1] = f2tf(Bs[n * SB + k8 + tig + 4]);
                }
            }
            #pragma unroll
            for (int mi = 0; mi < 4; mi++) {
                #pragma unroll
                for (int nj = 0; nj < 4; nj++) {
                    asm volatile(
                        "mma.sync.aligned.m16n8k8.row.col.f32.tf32.tf32.f32 "
                        "{%0,%1,%2,%3}, {%4,%5,%6,%7}, {%8,%9}, {%0,%1,%2,%3};"
                        : "+f"(acc[mi][nj][0]), "+f"(acc[mi][nj][1]),
                          "+f"(acc[mi][nj][2]), "+f"(acc[mi][nj][3])
                        : "r"(af[mi][0]), "r"(af[mi][1]), "r"(af[mi][2]), "r"(af[mi][3]),
                          "r"(bf[nj][0]), "r"(bf[nj][1]));
                }
            }
        }
    }

    // ---- epilogue ----
    #pragma unroll
    for (int mi = 0; mi < 4; mi++) {
        #pragma unroll
        for (int nj = 0; nj < 4; nj++) {
            int row = m0 + wm * 64 + mi * 16 + g;
            int col = n0 + wn * 32 + nj * 8 + tig * 2;
            size_t i00 = (size_t)row * Nc + col;
            size_t i10 = (size_t)(row + 8) * Nc + col;
            if (EPI == 0) {
                Ce[i00]     = acc[mi][nj][0];
                Ce[i00 + 1] = acc[mi][nj][1];
                Ce[i10]     = acc[mi][nj][2];
                Ce[i10 + 1] = acc[mi][nj][3];
            } else {
                float h00 = Se[i00], h01 = Se[i00 + 1];
                float h10 = Se[i10], h11 = Se[i10 + 1];
                // store mid pre-rounded to tf32 so GEMM3's A needs no cvt
                Ce[i00]     = __uint_as_float(f2tf(silu(h00) * acc[mi][nj][0]));
                Ce[i00 + 1] = __uint_as_float(f2tf(silu(h01) * acc[mi][nj][1]));
                Ce[i10]     = __uint_as_float(f2tf(silu(h10) * acc[mi][nj][2]));
                Ce[i10 + 1] = __uint_as_float(f2tf(silu(h11) * acc[mi][nj][3]));
            }
        }
    }
}

extern "C" void kernel_launch(void* const* d_in, const int* in_sizes, int n_in,
                              void* d_out, int out_size)
{
    const float* x  = (const float*)d_in[0];
    const float* w1 = (const float*)d_in[1];
    const float* w2 = (const float*)d_in[2];
    const float* w3 = (const float*)d_in[3];
    float* out = (float*)d_out;

    float* s1 = nullptr;
    float* s2 = nullptr;
    cudaGetSymbolAddress((void**)&s1, g_s1);   // no allocation; capture-safe
    cudaGetSymbolAddress((void**)&s2, g_s2);

    // dynamic smem: 3 stages * (A tile + B tile)
    constexpr size_t SM0 = 3 * (size_t)(128 * 36 + 32 * 136) * sizeof(float);   // 107520
    constexpr size_t SM1 = 3 * (size_t)(128 * 36 + 128 * 36) * sizeof(float);   // 110592
    cudaFuncSetAttribute(gemm_tf32<0, 0, NH, ND>, cudaFuncAttributeMaxDynamicSharedMemorySize, SM0);
    cudaFuncSetAttribute(gemm_tf32<0, 1, NH, ND>, cudaFuncAttributeMaxDynamicSharedMemorySize, SM0);
    cudaFuncSetAttribute(gemm_tf32<1, 0, ND, NH>, cudaFuncAttributeMaxDynamicSharedMemorySize, SM1);

    dim3 blk(256);
    dim3 g0(NH / 128, NT / 128, NE);   // (64, 2, 8)
    dim3 g1(ND / 128, NT / 128, NE);   // (16, 2, 8)

    // 0) pre-round x to tf32 (one cheap pass; A operand of GEMM1/2)
    int n4 = NE * NT * ND / 4;
    round_tf32<<<(n4 + 255) / 256, 256>>>(x, s2, n4);

    // 1) h1 = x @ w1                                -> s1 (raw fp32)
    gemm_tf32<0, 0, NH, ND><<<g0, blk, SM0>>>(s2, w1, s1, s1);
    // 2) mid = round(silu(h1) * (x @ w3))           -> s1 (tf32-rounded, in place)
    gemm_tf32<0, 1, NH, ND><<<g0, blk, SM0>>>(s2, w3, s1, s1);
    // 3) out = mid @ w2^T
    gemm_tf32<1, 0, ND, NH><<<g1, blk, SM1>>>(s1, w2, out, out);
}